// round 5
// baseline (speedup 1.0000x reference)
#include <cuda_runtime.h>
#include <cstdint>

#define BB 32
#define TT 800
#define LL 60
#define HH 512
#define DD 1024
#define AA 512
#define FCN 16
#define KCV 101
#define CC 4000
#define NB 148
#define NT 512

typedef unsigned long long ull;

// ---------------- static device scratch ----------------
__device__ float g_hE[BB * TT * AA];
__device__ float g_recpre[BB * LL * 2048];
__device__ float g_Wscat[3072 * 512];
__device__ float g_Wgcat[2560 * 1024];
__device__ float g_scat[BB * 3072];
__device__ float g_gcat[BB * 2560];
__device__ float g_gp2[8 * BB * DD];
__device__ float g_e[BB * TT];
__device__ float g_alpha[BB * TT];
__device__ float g_sT[HH * BB];
__device__ float g_ypre_all[LL * BB * HH];
__device__ float g_c[BB * HH];
__device__ volatile unsigned g_cnt;
__device__ volatile unsigned g_gen;

__device__ __forceinline__ void fma2(ull& d, ull a, ull b) {
    asm("fma.rn.f32x2 %0, %1, %2, %0;" : "+l"(d) : "l"(a), "l"(b));
}
__device__ __forceinline__ ull add2(ull a, ull b) {
    ull r;
    asm("add.rn.f32x2 %0, %1, %2;" : "=l"(r) : "l"(a), "l"(b));
    return r;
}
__device__ __forceinline__ ull pack2(float x) {
    ull r;
    asm("mov.b64 %0, {%1, %1};" : "=l"(r) : "f"(x));
    return r;
}
__device__ __forceinline__ float2 unpk(ull v) {
    float2 f;
    asm("mov.b64 {%0,%1}, %2;" : "=f"(f.x), "=f"(f.y) : "l"(v));
    return f;
}
__device__ __forceinline__ float ldcg(const float* p) {
    float v;
    asm volatile("ld.global.cg.f32 %0, [%1];" : "=f"(v) : "l"(p));
    return v;
}
__device__ __forceinline__ float4 ldcg4(const float* p) {
    float4 v;
    asm volatile("ld.global.cg.v4.f32 {%0,%1,%2,%3}, [%4];"
                 : "=f"(v.x), "=f"(v.y), "=f"(v.z), "=f"(v.w) : "l"(p));
    return v;
}
__device__ __forceinline__ float tanh_fast(float x) {
    float e2 = __expf(2.f * x);
    return 1.f - 2.f / (e2 + 1.f);
}
__device__ __forceinline__ float sig_acc(float x) {
    return tanhf(0.5f * x) * 0.5f + 0.5f;
}

__device__ __forceinline__ void gsync() {
    __syncthreads();
    if (threadIdx.x == 0) {
        unsigned gen = g_gen;
        __threadfence();
        if (atomicAdd((unsigned*)&g_cnt, 1u) == NB - 1) {
            g_cnt = 0;
            __threadfence();
            g_gen = gen + 1;
        } else {
            while (g_gen == gen) {}
        }
        __threadfence();
    }
    __syncthreads();
}

// ---------------- init ----------------
__global__ void k_init(const float* __restrict__ W_se, const float* __restrict__ W_sy,
                       const float* __restrict__ W_ss, const float* __restrict__ W_gy,
                       const float* __restrict__ W_gs) {
    int i0 = blockIdx.x * blockDim.x + threadIdx.x;
    int st = gridDim.x * blockDim.x;
    for (int i = i0; i < BB * HH; i += st) { g_c[i] = 0.f; g_sT[i] = 0.f; }
    for (int i = i0; i < BB * TT; i += st) g_alpha[i] = 0.f;
    for (int i = i0; i < 3072 * 512; i += st) {
        int r = i >> 9, k = i & 511;
        float v;
        if (r < 512)       v = W_se[i];
        else if (r < 1024) v = W_sy[(r - 512) * 512 + k];
        else               v = W_ss[(r - 1024) * 512 + k];
        g_Wscat[i] = v;
    }
    for (int i = i0; i < 2560 * 1024; i += st) {
        int r = i >> 10, k = i & 1023;
        g_Wgcat[i] = (r < 512) ? W_gy[i] : W_gs[(r - 512) * 1024 + k];
    }
}

// ---------------- big GEMM (FFMA2): Out[M,N]=A[M,K]@W[N,K]^T ----------------
template <int MODE>
__global__ __launch_bounds__(256) void k_gemm_big(
    const float* __restrict__ A, const float* __restrict__ W,
    const float* __restrict__ bias, float* __restrict__ outx,
    int lda, int ldw, int K) {
    __shared__ __align__(16) float As[16][132];
    __shared__ __align__(16) float Bs[16][132];
    const float* Ap = (MODE == 2) ? g_ypre_all : A;
    int t = threadIdx.x;
    int n0 = blockIdx.x * 128, m0 = blockIdx.y * 128;
    int tr = t >> 4, tc = t & 15;
    ull acc2[4][8];
#pragma unroll
    for (int i = 0; i < 4; i++)
#pragma unroll
        for (int j = 0; j < 8; j++) acc2[i][j] = 0ull;

    for (int k0 = 0; k0 < K; k0 += 16) {
#pragma unroll
        for (int j = 0; j < 8; j++) {
            int e = t + j * 256;
            int m = e >> 4, k = e & 15;
            As[k][m] = Ap[(size_t)(m0 + m) * lda + k0 + k];
            int n = n0 + m;
            float wv = 0.f;
            if (MODE != 2 || n < CC) wv = W[(size_t)n * ldw + k0 + k];
            Bs[k][m] = wv;
        }
        __syncthreads();
#pragma unroll
        for (int k = 0; k < 16; k++) {
            ulonglong2 aA = *(const ulonglong2*)&As[k][tr * 8];
            ulonglong2 aB = *(const ulonglong2*)&As[k][tr * 8 + 4];
            ull ap[4] = {aA.x, aA.y, aB.x, aB.y};
            float4 b0 = *(const float4*)&Bs[k][tc * 8];
            float4 b1 = *(const float4*)&Bs[k][tc * 8 + 4];
            ull bp[8] = {pack2(b0.x), pack2(b0.y), pack2(b0.z), pack2(b0.w),
                         pack2(b1.x), pack2(b1.y), pack2(b1.z), pack2(b1.w)};
#pragma unroll
            for (int i = 0; i < 4; i++)
#pragma unroll
                for (int j = 0; j < 8; j++) fma2(acc2[i][j], ap[i], bp[j]);
        }
        __syncthreads();
    }
#pragma unroll
    for (int mp = 0; mp < 4; mp++) {
        float r0[8], r1[8];
#pragma unroll
        for (int j = 0; j < 8; j++) {
            float2 v = unpk(acc2[mp][j]);
            int n = n0 + tc * 8 + j;
            float bv = (MODE == 0) ? 0.f : ((MODE == 2 && n >= CC) ? 0.f : bias[n]);
            r0[j] = v.x + bv;
            r1[j] = v.y + bv;
        }
        int me = m0 + tr * 8 + 2 * mp;
        int nn = n0 + tc * 8;
#pragma unroll
        for (int rr = 0; rr < 2; rr++) {
            int m = me + rr;
            const float* src = rr ? r1 : r0;
            float* orow;
            if (MODE == 0)      orow = &g_hE[(size_t)m * 512];
            else if (MODE == 1) orow = &g_recpre[(size_t)m * 2048];
            else {
                int l = m >> 5, b = m & 31;
                orow = outx + (size_t)b * LL * CC + (size_t)l * CC;
            }
            if (MODE != 2 || nn + 7 < CC) {
                *(float4*)&orow[nn] = make_float4(src[0], src[1], src[2], src[3]);
                *(float4*)&orow[nn + 4] = make_float4(src[4], src[5], src[6], src[7]);
            } else {
#pragma unroll
                for (int j = 0; j < 8; j++)
                    if (nn + j < CC) orow[nn + j] = src[j];
            }
        }
    }
}

// ---------------- persistent fused step loop ----------------
// smem layout (floats):
//  ws     @0      (21*512 = 10752)
//  wg     @10752  (18*1024 = 18432)
//  wfeT   @29184  (16*516  = 8256)
//  convw  @37440  (1616)
//  convb  @39056  (16)
//  wee    @39072  (512)
//  sE_s   @39584  (512)
//  alphaS @40096  (136, pad to 144)
//  AT     @40240  (256*36 = 9216)   total 49456 floats = 197824 B
#define SM_TOTALF 49456

__global__ __launch_bounds__(NT, 1) void k_steps(
    const int* __restrict__ lengths, const float* __restrict__ W_fe,
    const float* __restrict__ conv_w, const float* __restrict__ conv_b,
    const float* __restrict__ w_ee, const float* __restrict__ b_gy,
    const float* __restrict__ hbatch) {
    extern __shared__ float sm[];
    float* ws = sm;
    float* wg = sm + 10752;
    float* wfeT = sm + 29184;
    float* convw = sm + 37440;
    float* convb = sm + 39056;
    float* wee = sm + 39072;
    float* sE_s = sm + 39584;
    float* alphaS = sm + 40096;
    float* AT = sm + 40240;

    int bk = blockIdx.x, tid = threadIdx.x;
    int warp = tid >> 5, lane = tid & 31, mp = lane & 15, kh = lane >> 4;
    int n0s = bk * 20 + min(bk, 112), ncs = 20 + (bk < 112 ? 1 : 0);
    int n0g = bk * 17 + min(bk, 44),  ncg = 17 + (bk < 44 ? 1 : 0);

    for (int i = tid; i < ncs * 512; i += NT) ws[i] = g_Wscat[(size_t)n0s * 512 + i];
    for (int i = tid; i < ncg * 1024; i += NT) wg[i] = g_Wgcat[(size_t)n0g * 1024 + i];
    for (int i = tid; i < AA * FCN; i += NT) {
        int a = i >> 4, f = i & 15;
        wfeT[f * 516 + a] = W_fe[i];
    }
    for (int i = tid; i < FCN * KCV; i += NT) convw[i] = conv_w[i];
    if (tid < FCN) convb[tid] = conv_b[tid];
    for (int i = tid; i < AA; i += NT) wee[i] = w_ee[i];
    __syncthreads();

    for (int l = 0; l < LL; l++) {
        // ===== P1: scat = s @ Wscat^T (from SMEM weights) =====
        {
            ull a0e = 0, a0o = 0, a1e = 0, a1o = 0;
            for (int sp = 0; sp < 2; sp++) {
                __syncthreads();
                for (int idx = tid; idx < 2048; idx += NT) {
                    int r = idx >> 3, m4 = (idx & 7) << 2;
                    float4 v = ldcg4(&g_sT[(sp * 256 + r) * 32 + m4]);
                    *(float4*)&AT[r * 36 + m4] = v;
                }
                __syncthreads();
#pragma unroll
                for (int cc = 0; cc < 2; cc++) {
                    int col = warp + (cc << 4);
                    if (col < ncs) {
                        const float* wrow = &ws[col * 512 + sp * 256 + kh * 128];
                        const float* arow = &AT[kh * 128 * 36 + 2 * mp];
                        ull ae = 0, ao = 0;
#pragma unroll
                        for (int k4 = 0; k4 < 32; k4++) {
                            float4 w4 = *(const float4*)&wrow[k4 * 4];
                            ull p0 = *(const ull*)&arow[(k4 * 4 + 0) * 36];
                            ull p1 = *(const ull*)&arow[(k4 * 4 + 1) * 36];
                            ull p2 = *(const ull*)&arow[(k4 * 4 + 2) * 36];
                            ull p3 = *(const ull*)&arow[(k4 * 4 + 3) * 36];
                            fma2(ae, p0, pack2(w4.x));
                            fma2(ao, p1, pack2(w4.y));
                            fma2(ae, p2, pack2(w4.z));
                            fma2(ao, p3, pack2(w4.w));
                        }
                        if (cc == 0) { a0e = add2(a0e, ae); a0o = add2(a0o, ao); }
                        else         { a1e = add2(a1e, ae); a1o = add2(a1o, ao); }
                    }
                }
            }
            float2 r0 = unpk(add2(a0e, a0o));
            r0.x += __shfl_xor_sync(~0u, r0.x, 16);
            r0.y += __shfl_xor_sync(~0u, r0.y, 16);
            if (kh == 0 && warp < ncs) {
                g_scat[(2 * mp) * 3072 + n0s + warp] = r0.x;
                g_scat[(2 * mp + 1) * 3072 + n0s + warp] = r0.y;
            }
            float2 r1 = unpk(add2(a1e, a1o));
            r1.x += __shfl_xor_sync(~0u, r1.x, 16);
            r1.y += __shfl_xor_sync(~0u, r1.y, 16);
            int col = warp + 16;
            if (kh == 0 && col < ncs) {
                g_scat[(2 * mp) * 3072 + n0s + col] = r1.x;
                g_scat[(2 * mp + 1) * 3072 + n0s + col] = r1.y;
            }
        }
        gsync();

        // ===== P2: attention scoring =====
        for (int it = bk; it < 800; it += NB) {
            int b = it & 31, t0 = (it >> 5) << 5;
            int len = lengths[b];
            bool active = (t0 < len);
            __syncthreads();
            if (active) {
                for (int a = tid; a < AA; a += NT) sE_s[a] = ldcg(&g_scat[b * 3072 + a]);
                if (tid < 132) {
                    int tg = t0 - 50 + tid;
                    alphaS[tid] = (tg >= 0 && tg < TT) ? ldcg(&g_alpha[b * TT + tg]) : 0.f;
                }
            }
            __syncthreads();
            if (!active) {
                if (tid < 32) g_e[b * TT + t0 + tid] = -1e30f;
                continue;
            }
            for (int tt = warp; tt < 32; tt += 16) {
                int tabs = t0 + tt;
                if (tabs >= len) {
                    if (lane == 0) g_e[b * TT + tabs] = -1e30f;
                    continue;
                }
                int f = lane & 15, half = lane >> 4;
                float yp = 0.f;
                int ksb = half * 51, ke = half ? KCV : 51;
                for (int k = ksb; k < ke; k++)
                    yp = fmaf(alphaS[tt + k], convw[f * KCV + k], yp);
                yp += __shfl_down_sync(~0u, yp, 16);
                if (half == 0) yp += convb[f];
                ull yp2[16];
#pragma unroll
                for (int ff = 0; ff < 16; ff++) yp2[ff] = pack2(__shfl_sync(~0u, yp, ff));
                const float* hEr = g_hE + ((size_t)b * TT + tabs) * AA;
                ull v2[8];
#pragma unroll
                for (int c = 0; c < 4; c++) {
                    ulonglong2 h2 = *(const ulonglong2*)&hEr[c * 128 + lane * 4];
                    ulonglong2 s2 = *(const ulonglong2*)&sE_s[c * 128 + lane * 4];
                    v2[2 * c] = add2(h2.x, s2.x);
                    v2[2 * c + 1] = add2(h2.y, s2.y);
                }
#pragma unroll
                for (int ff = 0; ff < 16; ff++) {
#pragma unroll
                    for (int c = 0; c < 4; c++) {
                        ulonglong2 w2 = *(const ulonglong2*)&wfeT[ff * 516 + c * 128 + lane * 4];
                        fma2(v2[2 * c], yp2[ff], w2.x);
                        fma2(v2[2 * c + 1], yp2[ff], w2.y);
                    }
                }
                float accv = 0.f;
#pragma unroll
                for (int c = 0; c < 4; c++) {
                    float4 we = *(const float4*)&wee[c * 128 + lane * 4];
                    float2 q0 = unpk(v2[2 * c]);
                    float2 q1 = unpk(v2[2 * c + 1]);
                    accv = fmaf(tanh_fast(q0.x), we.x, accv);
                    accv = fmaf(tanh_fast(q0.y), we.y, accv);
                    accv = fmaf(tanh_fast(q1.x), we.z, accv);
                    accv = fmaf(tanh_fast(q1.y), we.w, accv);
                }
#pragma unroll
                for (int off = 16; off; off >>= 1) accv += __shfl_down_sync(~0u, accv, off);
                if (lane == 0) g_e[b * TT + tabs] = accv;
            }
        }
        gsync();

        // ===== P3: softmax (blocks 0..31) =====
        if (bk < 32) {
            int b = bk;
            float* es = AT;
            float* red = AT + 1024;
            float mx = -3e38f;
            for (int t2 = tid; t2 < TT; t2 += NT) {
                float v = ldcg(&g_e[b * TT + t2]);
                es[t2] = v;
                mx = fmaxf(mx, v);
            }
#pragma unroll
            for (int o = 16; o; o >>= 1) mx = fmaxf(mx, __shfl_xor_sync(~0u, mx, o));
            if (lane == 0) red[warp] = mx;
            __syncthreads();
            if (warp == 0) {
                float v = red[lane & 15];
#pragma unroll
                for (int o = 8; o; o >>= 1) v = fmaxf(v, __shfl_xor_sync(~0u, v, o));
                if (lane == 0) red[16] = v;
            }
            __syncthreads();
            float M = red[16];
            float sum = 0.f;
            for (int t2 = tid; t2 < TT; t2 += NT) {
                float p = __expf(es[t2] - M);
                es[t2] = p;
                sum += p;
            }
#pragma unroll
            for (int o = 16; o; o >>= 1) sum += __shfl_xor_sync(~0u, sum, o);
            if (lane == 0) red[warp] = sum;
            __syncthreads();
            if (warp == 0) {
                float v = red[lane & 15];
#pragma unroll
                for (int o = 8; o; o >>= 1) v += __shfl_xor_sync(~0u, v, o);
                if (lane == 0) red[17] = v;
            }
            __syncthreads();
            float inv = 1.f / red[17];
            for (int t2 = tid; t2 < TT; t2 += NT) g_alpha[b * TT + t2] = es[t2] * inv;
        }
        gsync();

        // ===== P4: gp2 partials (alpha @ hbatch) =====
        for (int it = bk; it < 256; it += NB) {
            int ts = it >> 5, b = it & 31;
            int len = lengths[b];
            int t1 = (len * ts) >> 3, t2e = (len * (ts + 1)) >> 3;
            int d = (tid & 255) * 4, tpar = tid >> 8;
            float4 acc = make_float4(0.f, 0.f, 0.f, 0.f);
            const float* hb = hbatch + (size_t)b * TT * DD + d;
            const float* al = g_alpha + b * TT;
            int t = t1 + tpar;
            for (; t + 2 < t2e; t += 4) {
                float a0 = ldcg(&al[t]);
                float a1 = ldcg(&al[t + 2]);
                float4 h0 = *(const float4*)&hb[(size_t)t * DD];
                float4 h1 = *(const float4*)&hb[(size_t)(t + 2) * DD];
                acc.x = fmaf(a0, h0.x, fmaf(a1, h1.x, acc.x));
                acc.y = fmaf(a0, h0.y, fmaf(a1, h1.y, acc.y));
                acc.z = fmaf(a0, h0.z, fmaf(a1, h1.z, acc.z));
                acc.w = fmaf(a0, h0.w, fmaf(a1, h1.w, acc.w));
            }
            if (t < t2e) {
                float a0 = ldcg(&al[t]);
                float4 h0 = *(const float4*)&hb[(size_t)t * DD];
                acc.x = fmaf(a0, h0.x, acc.x);
                acc.y = fmaf(a0, h0.y, acc.y);
                acc.z = fmaf(a0, h0.z, acc.z);
                acc.w = fmaf(a0, h0.w, acc.w);
            }
            __syncthreads();
            *(float4*)&AT[tid * 4] = acc;
            __syncthreads();
            if (tpar == 0) {
                float4 o = *(float4*)&AT[tid * 4];
                float4 p = *(float4*)&AT[(tid + 256) * 4];
                o.x += p.x; o.y += p.y; o.z += p.z; o.w += p.w;
                *(float4*)&g_gp2[(size_t)(ts * 32 + b) * 1024 + d] = o;
            }
        }
        gsync();

        // ===== P5: gcat = g @ Wgcat^T (from SMEM weights, 4 staged quarters) =====
        {
            ull a0e = 0, a0o = 0, a1e = 0, a1o = 0;
            for (int q = 0; q < 4; q++) {
                __syncthreads();
                for (int idx = tid; idx < 2048; idx += NT) {
                    int m = idx >> 6, r4 = (idx & 63) << 2;
                    float4 sa = make_float4(0.f, 0.f, 0.f, 0.f);
#pragma unroll
                    for (int p = 0; p < 8; p++) {
                        float4 v = ldcg4(&g_gp2[(size_t)(p * 32 + m) * 1024 + q * 256 + r4]);
                        sa.x += v.x; sa.y += v.y; sa.z += v.z; sa.w += v.w;
                    }
                    AT[(r4 + 0) * 36 + m] = sa.x;
                    AT[(r4 + 1) * 36 + m] = sa.y;
                    AT[(r4 + 2) * 36 + m] = sa.z;
                    AT[(r4 + 3) * 36 + m] = sa.w;
                }
                __syncthreads();
#pragma unroll
                for (int cc = 0; cc < 2; cc++) {
                    int col = warp + (cc << 4);
                    if (col < ncg) {
                        const float* wrow = &wg[col * 1024 + q * 256 + kh * 128];
                        const float* arow = &AT[kh * 128 * 36 + 2 * mp];
                        ull ae = 0, ao = 0;
#pragma unroll
                        for (int k4 = 0; k4 < 32; k4++) {
                            float4 w4 = *(const float4*)&wrow[k4 * 4];
                            ull p0 = *(const ull*)&arow[(k4 * 4 + 0) * 36];
                            ull p1 = *(const ull*)&arow[(k4 * 4 + 1) * 36];
                            ull p2 = *(const ull*)&arow[(k4 * 4 + 2) * 36];
                            ull p3 = *(const ull*)&arow[(k4 * 4 + 3) * 36];
                            fma2(ae, p0, pack2(w4.x));
                            fma2(ao, p1, pack2(w4.y));
                            fma2(ae, p2, pack2(w4.z));
                            fma2(ao, p3, pack2(w4.w));
                        }
                        if (cc == 0) { a0e = add2(a0e, ae); a0o = add2(a0o, ao); }
                        else         { a1e = add2(a1e, ae); a1o = add2(a1o, ao); }
                    }
                }
            }
            float2 r0 = unpk(add2(a0e, a0o));
            r0.x += __shfl_xor_sync(~0u, r0.x, 16);
            r0.y += __shfl_xor_sync(~0u, r0.y, 16);
            if (kh == 0 && warp < ncg) {
                g_gcat[(2 * mp) * 2560 + n0g + warp] = r0.x;
                g_gcat[(2 * mp + 1) * 2560 + n0g + warp] = r0.y;
            }
            float2 r1 = unpk(add2(a1e, a1o));
            r1.x += __shfl_xor_sync(~0u, r1.x, 16);
            r1.y += __shfl_xor_sync(~0u, r1.y, 16);
            int col = warp + 16;
            if (kh == 0 && col < ncg) {
                g_gcat[(2 * mp) * 2560 + n0g + col] = r1.x;
                g_gcat[(2 * mp + 1) * 2560 + n0g + col] = r1.y;
            }
        }
        gsync();

        // ===== P6: LSTM cell (blocks 0..31) =====
        if (bk < 32) {
            int b = bk, h = tid;
            float gy = ldcg(&g_gcat[b * 2560 + h]);
            float sy = ldcg(&g_scat[b * 3072 + 512 + h]);
            float ypre = tanhf(gy + sy + b_gy[h]);
            g_ypre_all[((size_t)l * 32 + b) * 512 + h] = ypre;
            float r[4];
#pragma unroll
            for (int qq = 0; qq < 4; qq++) {
                int j = qq * 512 + h;
                r[qq] = g_recpre[((size_t)b * LL + l) * 2048 + j]
                      + ldcg(&g_scat[b * 3072 + 1024 + j])
                      + ldcg(&g_gcat[b * 2560 + 512 + j]);
            }
            float cold = ldcg(&g_c[b * 512 + h]);
            float c = sig_acc(r[1]) * cold + sig_acc(r[0]) * tanhf(r[2]);
            float s = sig_acc(r[3]) * tanhf(c);
            g_c[b * 512 + h] = c;
            g_sT[h * 32 + b] = s;
        }
        gsync();
    }
}

// ---------------- launch ----------------
extern "C" void kernel_launch(void* const* d_in, const int* in_sizes, int n_in,
                              void* d_out, int out_size) {
    const float* hbatch  = (const float*)d_in[0];
    const int*   lengths = (const int*)d_in[1];
    const float* targets = (const float*)d_in[2];
    const float* W_sy    = (const float*)d_in[3];
    const float* W_gy    = (const float*)d_in[4];
    const float* b_gy    = (const float*)d_in[5];
    const float* W_yy    = (const float*)d_in[6];
    const float* b_yy    = (const float*)d_in[7];
    const float* W_ys    = (const float*)d_in[8];
    const float* W_ss    = (const float*)d_in[9];
    const float* W_gs    = (const float*)d_in[10];
    const float* b_gs    = (const float*)d_in[11];
    const float* W_se    = (const float*)d_in[12];
    const float* W_he    = (const float*)d_in[13];
    const float* W_fe    = (const float*)d_in[14];
    const float* conv_w  = (const float*)d_in[15];
    const float* conv_b  = (const float*)d_in[16];
    const float* w_ee    = (const float*)d_in[17];
    float* out = (float*)d_out;

    static bool attr_set = false;
    if (!attr_set) {
        cudaFuncSetAttribute(k_steps, cudaFuncAttributeMaxDynamicSharedMemorySize,
                             SM_TOTALF * 4);
        attr_set = true;
    }

    k_init<<<2048, 256>>>(W_se, W_sy, W_ss, W_gy, W_gs);
    // hE = hbatch @ W_he^T : [25600,512], K=1024
    k_gemm_big<0><<<dim3(4, 200), 256>>>(hbatch, W_he, nullptr, nullptr, 1024, 1024, 1024);
    // recpre = targets @ W_ys^T + b_gs : [1920,2048], K=4000
    k_gemm_big<1><<<dim3(16, 15), 256>>>(targets, W_ys, b_gs, nullptr, 4000, 4000, 4000);
    // fused 60-step decoder
    k_steps<<<NB, NT, SM_TOTALF * 4>>>(lengths, W_fe, conv_w, conv_b, w_ee, b_gy, hbatch);
    // y = ypre_all @ W_yy^T + b_yy : [1920,4000], K=512 -> out
    k_gemm_big<2><<<dim3(32, 15), 256>>>(nullptr, W_yy, b_yy, out, 512, 512, 512);
}

// round 6
// speedup vs baseline: 1.6250x; 1.6250x over previous
#include <cuda_runtime.h>
#include <cstdint>

#define BB 32
#define TT 800
#define LL 60
#define HH 512
#define DD 1024
#define AA 512
#define FCN 16
#define KCV 101
#define CC 4000
#define NSPK 8
#define NSPT 16

typedef unsigned long long ull;

// ---------------- static device scratch ----------------
__device__ float g_hE[BB * TT * AA];
__device__ float g_recpre[BB * LL * 2048];
__device__ float g_Wscat[3072 * 512];
__device__ float g_Wgcat[2560 * 1024];
__device__ float g_spart[NSPK * BB * 3072];
__device__ float g_gpart[NSPK * BB * 2560];
__device__ float g_scat[BB * 3072];
__device__ float g_gp2[NSPT * BB * DD];
__device__ float g_g[BB * DD];
__device__ float g_e[BB * TT];
__device__ float g_alpha[BB * TT];
__device__ float g_ypre_all[LL * BB * HH];
__device__ float g_s[BB * HH];
__device__ float g_c[BB * HH];

__device__ __forceinline__ void fma2(ull& d, ull a, ull b) {
    asm("fma.rn.f32x2 %0, %1, %2, %0;" : "+l"(d) : "l"(a), "l"(b));
}
__device__ __forceinline__ ull add2(ull a, ull b) {
    ull r;
    asm("add.rn.f32x2 %0, %1, %2;" : "=l"(r) : "l"(a), "l"(b));
    return r;
}
__device__ __forceinline__ ull pack2(float x) {
    ull r;
    asm("mov.b64 %0, {%1, %1};" : "=l"(r) : "f"(x));
    return r;
}
__device__ __forceinline__ float2 unpk(ull v) {
    float2 f;
    asm("mov.b64 {%0,%1}, %2;" : "=f"(f.x), "=f"(f.y) : "l"(v));
    return f;
}
__device__ __forceinline__ float tanh_fast(float x) {
    float e2 = __expf(2.f * x);
    return 1.f - 2.f / (e2 + 1.f);
}
__device__ __forceinline__ float sig_acc(float x) {
    return tanhf(0.5f * x) * 0.5f + 0.5f;
}

// ---------------- init ----------------
__global__ void k_init(const float* __restrict__ W_se, const float* __restrict__ W_sy,
                       const float* __restrict__ W_ss, const float* __restrict__ W_gy,
                       const float* __restrict__ W_gs) {
    int i0 = blockIdx.x * blockDim.x + threadIdx.x;
    int st = gridDim.x * blockDim.x;
    for (int i = i0; i < BB * HH; i += st) { g_s[i] = 0.f; g_c[i] = 0.f; }
    for (int i = i0; i < BB * TT; i += st) g_alpha[i] = 0.f;
    for (int i = i0; i < 3072 * 512; i += st) {
        int r = i >> 9, k = i & 511;
        float v;
        if (r < 512)       v = W_se[i];
        else if (r < 1024) v = W_sy[(r - 512) * 512 + k];
        else               v = W_ss[(r - 1024) * 512 + k];
        g_Wscat[i] = v;
    }
    for (int i = i0; i < 2560 * 1024; i += st) {
        int r = i >> 10, k = i & 1023;
        g_Wgcat[i] = (r < 512) ? W_gy[i] : W_gs[(r - 512) * 1024 + k];
    }
}

// ---------------- big GEMM (FFMA2): Out[M,N]=A[M,K]@W[N,K]^T ----------------
template <int MODE>
__global__ __launch_bounds__(256) void k_gemm_big(
    const float* __restrict__ A, const float* __restrict__ W,
    const float* __restrict__ bias, float* __restrict__ outx,
    int lda, int ldw, int K) {
    __shared__ __align__(16) float As[16][132];
    __shared__ __align__(16) float Bs[16][132];
    const float* Ap = (MODE == 2) ? g_ypre_all : A;
    int t = threadIdx.x;
    int n0 = blockIdx.x * 128, m0 = blockIdx.y * 128;
    int tr = t >> 4, tc = t & 15;
    ull acc2[4][8];
#pragma unroll
    for (int i = 0; i < 4; i++)
#pragma unroll
        for (int j = 0; j < 8; j++) acc2[i][j] = 0ull;

    for (int k0 = 0; k0 < K; k0 += 16) {
#pragma unroll
        for (int j = 0; j < 8; j++) {
            int e = t + j * 256;
            int m = e >> 4, k = e & 15;
            As[k][m] = Ap[(size_t)(m0 + m) * lda + k0 + k];
            int n = n0 + m;
            float wv = 0.f;
            if (MODE != 2 || n < CC) wv = W[(size_t)n * ldw + k0 + k];
            Bs[k][m] = wv;
        }
        __syncthreads();
#pragma unroll
        for (int k = 0; k < 16; k++) {
            ulonglong2 aA = *(const ulonglong2*)&As[k][tr * 8];
            ulonglong2 aB = *(const ulonglong2*)&As[k][tr * 8 + 4];
            ull ap[4] = {aA.x, aA.y, aB.x, aB.y};
            float4 b0 = *(const float4*)&Bs[k][tc * 8];
            float4 b1 = *(const float4*)&Bs[k][tc * 8 + 4];
            ull bp[8] = {pack2(b0.x), pack2(b0.y), pack2(b0.z), pack2(b0.w),
                         pack2(b1.x), pack2(b1.y), pack2(b1.z), pack2(b1.w)};
#pragma unroll
            for (int i = 0; i < 4; i++)
#pragma unroll
                for (int j = 0; j < 8; j++) fma2(acc2[i][j], ap[i], bp[j]);
        }
        __syncthreads();
    }
#pragma unroll
    for (int mp = 0; mp < 4; mp++) {
        float r0[8], r1[8];
#pragma unroll
        for (int j = 0; j < 8; j++) {
            float2 v = unpk(acc2[mp][j]);
            int n = n0 + tc * 8 + j;
            float bv = (MODE == 0) ? 0.f : ((MODE == 2 && n >= CC) ? 0.f : bias[n]);
            r0[j] = v.x + bv;
            r1[j] = v.y + bv;
        }
        int me = m0 + tr * 8 + 2 * mp;
        int nn = n0 + tc * 8;
#pragma unroll
        for (int rr = 0; rr < 2; rr++) {
            int m = me + rr;
            const float* src = rr ? r1 : r0;
            float* orow;
            if (MODE == 0)      orow = &g_hE[(size_t)m * 512];
            else if (MODE == 1) orow = &g_recpre[(size_t)m * 2048];
            else {
                int l = m >> 5, b = m & 31;
                orow = outx + (size_t)b * LL * CC + (size_t)l * CC;
            }
            if (MODE != 2 || nn + 7 < CC) {
                *(float4*)&orow[nn] = make_float4(src[0], src[1], src[2], src[3]);
                *(float4*)&orow[nn + 4] = make_float4(src[4], src[5], src[6], src[7]);
            } else {
#pragma unroll
                for (int j = 0; j < 8; j++)
                    if (nn + j < CC) orow[nn + j] = src[j];
            }
        }
    }
}

// ---------------- skinny GEMM: thread-per-n streaming, k-split 8, single wave ----------------
// MODE 0: s @ Wscat^T (N=3072,K=512,KS=64)  grid (12,8)
// MODE 1: g @ Wgcat^T (N=2560,K=1024,KS=128) grid (10,8)
template <int MODE>
__global__ __launch_bounds__(256) void k_skinny() {
    constexpr int N = MODE ? 2560 : 3072;
    constexpr int K = MODE ? 1024 : 512;
    constexpr int KS = K / NSPK;
    __shared__ __align__(16) float As[KS][36];
    int tid = threadIdx.x;
    int n = blockIdx.x * 256 + tid;
    int z = blockIdx.y, kb = z * KS;
    const float* W = MODE ? g_Wgcat : g_Wscat;
    const float* Ain = MODE ? g_g : g_s;
    float* Out = MODE ? (g_gpart + z * BB * 2560) : (g_spart + z * BB * 3072);
    for (int i = tid; i < 32 * KS; i += 256) {
        int m = i / KS, k = i % KS;
        As[k][m] = Ain[m * K + kb + k];
    }
    __syncthreads();
    ull acc[16];
#pragma unroll
    for (int mp = 0; mp < 16; mp++) acc[mp] = 0ull;
    const float* Wr = &W[(size_t)n * K + kb];
#pragma unroll 8
    for (int k4 = 0; k4 < KS / 4; k4++) {
        float4 w4 = *(const float4*)&Wr[k4 * 4];
        float wf[4] = {w4.x, w4.y, w4.z, w4.w};
#pragma unroll
        for (int q = 0; q < 4; q++) {
            ull wp = pack2(wf[q]);
            int k = k4 * 4 + q;
#pragma unroll
            for (int mp = 0; mp < 16; mp++) {
                ull a = *(const ull*)&As[k][2 * mp];
                fma2(acc[mp], a, wp);
            }
        }
    }
#pragma unroll
    for (int mp = 0; mp < 16; mp++) {
        float2 v = unpk(acc[mp]);
        Out[(2 * mp) * N + n] = v.x;
        Out[(2 * mp + 1) * N + n] = v.y;
    }
}

// ---------------- reduce k-split partials of scat -> g_scat ----------------
__global__ __launch_bounds__(256) void k_reds() {
    int i = (blockIdx.x * 256 + threadIdx.x) * 4;   // grid 96: covers 32*3072
    float4 acc = make_float4(0.f, 0.f, 0.f, 0.f);
#pragma unroll
    for (int p = 0; p < NSPK; p++) {
        float4 v = *(const float4*)&g_spart[p * BB * 3072 + i];
        acc.x += v.x; acc.y += v.y; acc.z += v.z; acc.w += v.w;
    }
    *(float4*)&g_scat[i] = acc;
}

// ---------------- reduce t-split partials of g -> g_g ----------------
__global__ void k_gsum() {
    int b = blockIdx.x, d = threadIdx.x * 4;
    float4 acc = make_float4(0.f, 0.f, 0.f, 0.f);
#pragma unroll
    for (int p = 0; p < NSPT; p++) {
        float4 x = *(const float4*)&g_gp2[p * BB * DD + b * DD + d];
        acc.x += x.x; acc.y += x.y; acc.z += x.z; acc.w += x.w;
    }
    *(float4*)&g_g[b * DD + d] = acc;
}

// ---------------- fused attention scoring ----------------
__global__ __launch_bounds__(256) void k_attn(const int* __restrict__ lengths,
                                              const float* __restrict__ W_fe,
                                              const float* __restrict__ conv_w,
                                              const float* __restrict__ conv_b,
                                              const float* __restrict__ w_ee) {
    __shared__ float sE_s[AA];
    __shared__ float wee_s[AA];
    __shared__ float convw_s[FCN * KCV];
    __shared__ float convb_s[FCN];
    __shared__ float alpha_s[132];
    __shared__ __align__(16) float WfeT[FCN * 516];
    int b = blockIdx.y;
    int t0 = blockIdx.x * 32;
    int tid = threadIdx.x;
    int len = lengths[b];
    if (t0 >= len) {
        if (tid < 32) g_e[b * TT + t0 + tid] = -1e30f;
        return;
    }
    for (int a = tid; a < AA; a += 256) {
        sE_s[a] = g_scat[b * 3072 + a];
        wee_s[a] = w_ee[a];
    }
    for (int i = tid; i < FCN * KCV; i += 256) convw_s[i] = conv_w[i];
    if (tid < FCN) convb_s[tid] = conv_b[tid];
    for (int i = tid; i < AA * FCN; i += 256) {
        int a = i >> 4, f = i & 15;
        WfeT[f * 516 + a] = W_fe[i];
    }
    if (tid < 132) {
        int tg = t0 - 50 + tid;
        alpha_s[tid] = (tg >= 0 && tg < TT) ? g_alpha[b * TT + tg] : 0.f;
    }
    __syncthreads();
    int w = tid >> 5, lane = tid & 31;
    for (int tt = w; tt < 32; tt += 8) {
        int tabs = t0 + tt;
        if (tabs >= len) {
            if (lane == 0) g_e[b * TT + tabs] = -1e30f;
            continue;
        }
        int f = lane & 15, half = lane >> 4;
        float yp = 0.f;
        int ks = half * 51, ke = half ? KCV : 51;
        for (int k = ks; k < ke; k++)
            yp = fmaf(alpha_s[tt + k], convw_s[f * KCV + k], yp);
        yp += __shfl_down_sync(0xffffffffu, yp, 16);
        if (half == 0) yp += convb_s[f];
        ull yp2[16];
#pragma unroll
        for (int ff = 0; ff < 16; ff++) yp2[ff] = pack2(__shfl_sync(0xffffffffu, yp, ff));
        const float* hEr = g_hE + ((size_t)b * TT + tabs) * AA;
        ull v2[8];
#pragma unroll
        for (int c = 0; c < 4; c++) {
            ulonglong2 h2 = *(const ulonglong2*)&hEr[c * 128 + lane * 4];
            ulonglong2 s2 = *(const ulonglong2*)&sE_s[c * 128 + lane * 4];
            v2[2 * c] = add2(h2.x, s2.x);
            v2[2 * c + 1] = add2(h2.y, s2.y);
        }
#pragma unroll
        for (int ff = 0; ff < 16; ff++) {
#pragma unroll
            for (int c = 0; c < 4; c++) {
                ulonglong2 w2 = *(const ulonglong2*)&WfeT[ff * 516 + c * 128 + lane * 4];
                fma2(v2[2 * c], yp2[ff], w2.x);
                fma2(v2[2 * c + 1], yp2[ff], w2.y);
            }
        }
        float acc = 0.f;
#pragma unroll
        for (int c = 0; c < 4; c++) {
            float4 we = *(const float4*)&wee_s[c * 128 + lane * 4];
            float2 a0 = unpk(v2[2 * c]);
            float2 a1 = unpk(v2[2 * c + 1]);
            acc = fmaf(tanh_fast(a0.x), we.x, acc);
            acc = fmaf(tanh_fast(a0.y), we.y, acc);
            acc = fmaf(tanh_fast(a1.x), we.z, acc);
            acc = fmaf(tanh_fast(a1.y), we.w, acc);
        }
#pragma unroll
        for (int off = 16; off; off >>= 1) acc += __shfl_down_sync(0xffffffffu, acc, off);
        if (lane == 0) g_e[b * TT + tabs] = acc;
    }
}

// ---------------- fused softmax + g = alpha @ hbatch (t-split x16) ----------------
__global__ __launch_bounds__(256) void k_gaccum(const float* __restrict__ hbatch,
                                                const int* __restrict__ lengths) {
    int b = blockIdx.x, ts = blockIdx.y;
    int tid = threadIdx.x;
    __shared__ float es[TT];
    __shared__ float red[256];
    float mx = -3e38f;
    for (int t2 = tid; t2 < TT; t2 += 256) {
        float v = g_e[b * TT + t2];
        es[t2] = v;
        mx = fmaxf(mx, v);
    }
    red[tid] = mx;
    __syncthreads();
    for (int o = 128; o; o >>= 1) {
        if (tid < o) red[tid] = fmaxf(red[tid], red[tid + o]);
        __syncthreads();
    }
    float M = red[0];
    __syncthreads();
    float sm = 0.f;
    for (int t2 = tid; t2 < TT; t2 += 256) {
        float p = __expf(es[t2] - M);
        es[t2] = p;
        sm += p;
    }
    red[tid] = sm;
    __syncthreads();
    for (int o = 128; o; o >>= 1) {
        if (tid < o) red[tid] += red[tid + o];
        __syncthreads();
    }
    float inv = 1.f / red[0];
    __syncthreads();
    for (int t2 = tid; t2 < TT; t2 += 256) es[t2] *= inv;
    __syncthreads();
    if (ts == 0)
        for (int t2 = tid; t2 < TT; t2 += 256) g_alpha[b * TT + t2] = es[t2];

    int len = lengths[b];
    int t1 = (len * ts) / NSPT, t2e = (len * (ts + 1)) / NSPT;
    int d = tid * 4;
    float4 acc = make_float4(0.f, 0.f, 0.f, 0.f);
    const float* hb = hbatch + (size_t)b * TT * DD + d;
    int t = t1;
    for (; t + 4 <= t2e; t += 4) {
        float a0 = es[t], a1 = es[t + 1], a2 = es[t + 2], a3 = es[t + 3];
        float4 h0 = *(const float4*)&hb[(size_t)t * DD];
        float4 h1 = *(const float4*)&hb[(size_t)(t + 1) * DD];
        float4 h2 = *(const float4*)&hb[(size_t)(t + 2) * DD];
        float4 h3 = *(const float4*)&hb[(size_t)(t + 3) * DD];
        acc.x = fmaf(a0, h0.x, fmaf(a1, h1.x, fmaf(a2, h2.x, fmaf(a3, h3.x, acc.x))));
        acc.y = fmaf(a0, h0.y, fmaf(a1, h1.y, fmaf(a2, h2.y, fmaf(a3, h3.y, acc.y))));
        acc.z = fmaf(a0, h0.z, fmaf(a1, h1.z, fmaf(a2, h2.z, fmaf(a3, h3.z, acc.z))));
        acc.w = fmaf(a0, h0.w, fmaf(a1, h1.w, fmaf(a2, h2.w, fmaf(a3, h3.w, acc.w))));
    }
    for (; t < t2e; t++) {
        float a0 = es[t];
        float4 h0 = *(const float4*)&hb[(size_t)t * DD];
        acc.x = fmaf(a0, h0.x, acc.x);
        acc.y = fmaf(a0, h0.y, acc.y);
        acc.z = fmaf(a0, h0.z, acc.z);
        acc.w = fmaf(a0, h0.w, acc.w);
    }
    *(float4*)&g_gp2[ts * BB * DD + b * DD + d] = acc;
}

// ---------------- LSTM cell + ypre ----------------
__global__ __launch_bounds__(512) void k_cell(const float* __restrict__ b_gy, int l) {
    int b = blockIdx.x, h = threadIdx.x;
    float gy = 0.f;
#pragma unroll
    for (int p = 0; p < NSPK; p++) gy += g_gpart[p * BB * 2560 + b * 2560 + h];
    float sy = g_scat[b * 3072 + 512 + h];
    float ypre = tanhf(gy + sy + b_gy[h]);
    g_ypre_all[((size_t)l * BB + b) * HH + h] = ypre;
    float r[4];
#pragma unroll
    for (int q = 0; q < 4; q++) {
        int j = q * 512 + h;
        float v = g_recpre[((size_t)b * LL + l) * 2048 + j] + g_scat[b * 3072 + 1024 + j];
#pragma unroll
        for (int p = 0; p < NSPK; p++) v += g_gpart[p * BB * 2560 + b * 2560 + 512 + j];
        r[q] = v;
    }
    float c = sig_acc(r[1]) * g_c[b * HH + h] + sig_acc(r[0]) * tanhf(r[2]);
    float s = sig_acc(r[3]) * tanhf(c);
    g_c[b * HH + h] = c;
    g_s[b * HH + h] = s;
}

// ---------------- launch ----------------
extern "C" void kernel_launch(void* const* d_in, const int* in_sizes, int n_in,
                              void* d_out, int out_size) {
    const float* hbatch  = (const float*)d_in[0];
    const int*   lengths = (const int*)d_in[1];
    const float* targets = (const float*)d_in[2];
    const float* W_sy    = (const float*)d_in[3];
    const float* W_gy    = (const float*)d_in[4];
    const float* b_gy    = (const float*)d_in[5];
    const float* W_yy    = (const float*)d_in[6];
    const float* b_yy    = (const float*)d_in[7];
    const float* W_ys    = (const float*)d_in[8];
    const float* W_ss    = (const float*)d_in[9];
    const float* W_gs    = (const float*)d_in[10];
    const float* b_gs    = (const float*)d_in[11];
    const float* W_se    = (const float*)d_in[12];
    const float* W_he    = (const float*)d_in[13];
    const float* W_fe    = (const float*)d_in[14];
    const float* conv_w  = (const float*)d_in[15];
    const float* conv_b  = (const float*)d_in[16];
    const float* w_ee    = (const float*)d_in[17];
    float* out = (float*)d_out;

    k_init<<<2048, 256>>>(W_se, W_sy, W_ss, W_gy, W_gs);
    // hE = hbatch @ W_he^T : [25600,512], K=1024
    k_gemm_big<0><<<dim3(4, 200), 256>>>(hbatch, W_he, nullptr, nullptr, 1024, 1024, 1024);
    // recpre = targets @ W_ys^T + b_gs : [1920,2048], K=4000
    k_gemm_big<1><<<dim3(16, 15), 256>>>(targets, W_ys, b_gs, nullptr, 4000, 4000, 4000);

    for (int l = 0; l < LL; l++) {
        k_skinny<0><<<dim3(12, NSPK), 256>>>();
        k_reds<<<96, 256>>>();
        k_attn<<<dim3(25, 32), 256>>>(lengths, W_fe, conv_w, conv_b, w_ee);
        k_gaccum<<<dim3(32, NSPT), 256>>>(hbatch, lengths);
        k_gsum<<<32, 256>>>();
        k_skinny<1><<<dim3(10, NSPK), 256>>>();
        k_cell<<<32, 512>>>(b_gy, l);
    }
    // y = ypre_all @ W_yy^T + b_yy : [1920,4000], K=512 -> out
    k_gemm_big<2><<<dim3(32, 15), 256>>>(nullptr, W_yy, b_yy, out, 512, 512, 512);
}

// round 7
// speedup vs baseline: 1.6742x; 1.0302x over previous
#include <cuda_runtime.h>
#include <cstdint>

#define BB 32
#define TT 800
#define LL 60
#define HH 512
#define DD 1024
#define AA 512
#define FCN 16
#define KCV 101
#define CC 4000
#define NSPK 8
#define NSPT 16

typedef unsigned long long ull;

// ---------------- static device scratch ----------------
__device__ float g_hE[BB * TT * AA];
__device__ float g_recpre[BB * LL * 2048];
__device__ float g_Wscat[3072 * 512];
__device__ float g_Wgcat[2560 * 1024];
__device__ float g_spart[NSPK * BB * 3072];
__device__ float g_gpart[NSPK * BB * 2560];
__device__ float g_gp2[NSPT * BB * DD];
__device__ float g_g[BB * DD];
__device__ float g_e[BB * TT];
__device__ float g_alpha[BB * TT];
__device__ float g_ypre_all[LL * BB * HH];
__device__ float g_s[BB * HH];
__device__ float g_c[BB * HH];

__device__ __forceinline__ void fma2(ull& d, ull a, ull b) {
    asm("fma.rn.f32x2 %0, %1, %2, %0;" : "+l"(d) : "l"(a), "l"(b));
}
__device__ __forceinline__ ull add2(ull a, ull b) {
    ull r;
    asm("add.rn.f32x2 %0, %1, %2;" : "=l"(r) : "l"(a), "l"(b));
    return r;
}
__device__ __forceinline__ ull pack2(float x) {
    ull r;
    asm("mov.b64 %0, {%1, %1};" : "=l"(r) : "f"(x));
    return r;
}
__device__ __forceinline__ float2 unpk(ull v) {
    float2 f;
    asm("mov.b64 {%0,%1}, %2;" : "=f"(f.x), "=f"(f.y) : "l"(v));
    return f;
}
__device__ __forceinline__ float tanh_fast(float x) {
    float e2 = __expf(2.f * x);
    return 1.f - 2.f / (e2 + 1.f);
}
__device__ __forceinline__ float sig_acc(float x) {
    return tanhf(0.5f * x) * 0.5f + 0.5f;
}

// ---------------- init ----------------
__global__ void k_init(const float* __restrict__ W_se, const float* __restrict__ W_sy,
                       const float* __restrict__ W_ss, const float* __restrict__ W_gy,
                       const float* __restrict__ W_gs) {
    int i0 = blockIdx.x * blockDim.x + threadIdx.x;
    int st = gridDim.x * blockDim.x;
    for (int i = i0; i < BB * HH; i += st) { g_s[i] = 0.f; g_c[i] = 0.f; }
    for (int i = i0; i < BB * TT; i += st) g_alpha[i] = 0.f;
    for (int i = i0; i < 3072 * 512; i += st) {
        int r = i >> 9, k = i & 511;
        float v;
        if (r < 512)       v = W_se[i];
        else if (r < 1024) v = W_sy[(r - 512) * 512 + k];
        else               v = W_ss[(r - 1024) * 512 + k];
        g_Wscat[i] = v;
    }
    for (int i = i0; i < 2560 * 1024; i += st) {
        int r = i >> 10, k = i & 1023;
        g_Wgcat[i] = (r < 512) ? W_gy[i] : W_gs[(r - 512) * 1024 + k];
    }
}

// ---------------- big GEMM (FFMA2): Out[M,N]=A[M,K]@W[N,K]^T ----------------
template <int MODE>
__global__ __launch_bounds__(256) void k_gemm_big(
    const float* __restrict__ A, const float* __restrict__ W,
    const float* __restrict__ bias, float* __restrict__ outx,
    int lda, int ldw, int K) {
    __shared__ __align__(16) float As[16][132];
    __shared__ __align__(16) float Bs[16][132];
    const float* Ap = (MODE == 2) ? g_ypre_all : A;
    int t = threadIdx.x;
    int n0 = blockIdx.x * 128, m0 = blockIdx.y * 128;
    int tr = t >> 4, tc = t & 15;
    ull acc2[4][8];
#pragma unroll
    for (int i = 0; i < 4; i++)
#pragma unroll
        for (int j = 0; j < 8; j++) acc2[i][j] = 0ull;

    for (int k0 = 0; k0 < K; k0 += 16) {
#pragma unroll
        for (int j = 0; j < 8; j++) {
            int e = t + j * 256;
            int m = e >> 4, k = e & 15;
            As[k][m] = Ap[(size_t)(m0 + m) * lda + k0 + k];
            int n = n0 + m;
            float wv = 0.f;
            if (MODE != 2 || n < CC) wv = W[(size_t)n * ldw + k0 + k];
            Bs[k][m] = wv;
        }
        __syncthreads();
#pragma unroll
        for (int k = 0; k < 16; k++) {
            ulonglong2 aA = *(const ulonglong2*)&As[k][tr * 8];
            ulonglong2 aB = *(const ulonglong2*)&As[k][tr * 8 + 4];
            ull ap[4] = {aA.x, aA.y, aB.x, aB.y};
            float4 b0 = *(const float4*)&Bs[k][tc * 8];
            float4 b1 = *(const float4*)&Bs[k][tc * 8 + 4];
            ull bp[8] = {pack2(b0.x), pack2(b0.y), pack2(b0.z), pack2(b0.w),
                         pack2(b1.x), pack2(b1.y), pack2(b1.z), pack2(b1.w)};
#pragma unroll
            for (int i = 0; i < 4; i++)
#pragma unroll
                for (int j = 0; j < 8; j++) fma2(acc2[i][j], ap[i], bp[j]);
        }
        __syncthreads();
    }
#pragma unroll
    for (int mp = 0; mp < 4; mp++) {
        float r0[8], r1[8];
#pragma unroll
        for (int j = 0; j < 8; j++) {
            float2 v = unpk(acc2[mp][j]);
            int n = n0 + tc * 8 + j;
            float bv = (MODE == 0) ? 0.f : ((MODE == 2 && n >= CC) ? 0.f : bias[n]);
            r0[j] = v.x + bv;
            r1[j] = v.y + bv;
        }
        int me = m0 + tr * 8 + 2 * mp;
        int nn = n0 + tc * 8;
#pragma unroll
        for (int rr = 0; rr < 2; rr++) {
            int m = me + rr;
            const float* src = rr ? r1 : r0;
            float* orow;
            if (MODE == 0)      orow = &g_hE[(size_t)m * 512];
            else if (MODE == 1) orow = &g_recpre[(size_t)m * 2048];
            else {
                int l = m >> 5, b = m & 31;
                orow = outx + (size_t)b * LL * CC + (size_t)l * CC;
            }
            if (MODE != 2 || nn + 7 < CC) {
                *(float4*)&orow[nn] = make_float4(src[0], src[1], src[2], src[3]);
                *(float4*)&orow[nn + 4] = make_float4(src[4], src[5], src[6], src[7]);
            } else {
#pragma unroll
                for (int j = 0; j < 8; j++)
                    if (nn + j < CC) orow[nn + j] = src[j];
            }
        }
    }
}

// ---------------- skinny GEMM: thread-per-n, front-loaded weight registers ----------------
// MODE 0: s @ Wscat^T (N=3072,K=512,KS=64)   grid (12,8), 1 batch of 16 LDG.128
// MODE 1: g @ Wgcat^T (N=2560,K=1024,KS=128) grid (10,8), 2 batches of 16 LDG.128
template <int MODE>
__global__ __launch_bounds__(256) void k_skinny() {
    constexpr int N = MODE ? 2560 : 3072;
    constexpr int K = MODE ? 1024 : 512;
    constexpr int KS = K / NSPK;
    constexpr int NBATCH = KS / 64;
    __shared__ __align__(16) float As[KS][36];
    int tid = threadIdx.x;
    int n = blockIdx.x * 256 + tid;
    int z = blockIdx.y, kb = z * KS;
    const float* W = MODE ? g_Wgcat : g_Wscat;
    const float* Ain = MODE ? g_g : g_s;
    float* Out = MODE ? (g_gpart + z * BB * 2560) : (g_spart + z * BB * 3072);
    const float* Wr = &W[(size_t)n * K + kb];

    // batch 0 weight loads issued before A staging -> overlap with LDS fill
    float4 w[16];
#pragma unroll
    for (int i = 0; i < 16; i++) w[i] = *(const float4*)&Wr[i * 4];

    for (int i = tid; i < 32 * KS; i += 256) {
        int m = i / KS, k = i % KS;
        As[k][m] = Ain[m * K + kb + k];
    }
    __syncthreads();

    ull acc[16];
#pragma unroll
    for (int mp = 0; mp < 16; mp++) acc[mp] = 0ull;

#pragma unroll
    for (int bt = 0; bt < NBATCH; bt++) {
        if (bt > 0) {
#pragma unroll
            for (int i = 0; i < 16; i++) w[i] = *(const float4*)&Wr[bt * 64 + i * 4];
        }
#pragma unroll
        for (int k4 = 0; k4 < 16; k4++) {
            float wf[4] = {w[k4].x, w[k4].y, w[k4].z, w[k4].w};
#pragma unroll
            for (int q = 0; q < 4; q++) {
                ull wp = pack2(wf[q]);
                int k = bt * 64 + k4 * 4 + q;
#pragma unroll
                for (int mp = 0; mp < 16; mp++) {
                    ull a = *(const ull*)&As[k][2 * mp];
                    fma2(acc[mp], a, wp);
                }
            }
        }
    }
#pragma unroll
    for (int mp = 0; mp < 16; mp++) {
        float2 v = unpk(acc[mp]);
        Out[(2 * mp) * N + n] = v.x;
        Out[(2 * mp + 1) * N + n] = v.y;
    }
}

// ---------------- reduce t-split partials of g -> g_g ----------------
__global__ void k_gsum() {
    int b = blockIdx.x, d = threadIdx.x * 4;
    float4 acc = make_float4(0.f, 0.f, 0.f, 0.f);
#pragma unroll
    for (int p = 0; p < NSPT; p++) {
        float4 x = *(const float4*)&g_gp2[p * BB * DD + b * DD + d];
        acc.x += x.x; acc.y += x.y; acc.z += x.z; acc.w += x.w;
    }
    *(float4*)&g_g[b * DD + d] = acc;
}

// ---------------- fused attention scoring (sums sE partials itself) ----------------
__global__ __launch_bounds__(256) void k_attn(const int* __restrict__ lengths,
                                              const float* __restrict__ W_fe,
                                              const float* __restrict__ conv_w,
                                              const float* __restrict__ conv_b,
                                              const float* __restrict__ w_ee) {
    __shared__ float sE_s[AA];
    __shared__ float wee_s[AA];
    __shared__ float convw_s[FCN * KCV];
    __shared__ float convb_s[FCN];
    __shared__ float alpha_s[132];
    __shared__ __align__(16) float WfeT[FCN * 516];
    int b = blockIdx.y;
    int t0 = blockIdx.x * 32;
    int tid = threadIdx.x;
    int len = lengths[b];
    if (t0 >= len) {
        if (tid < 32) g_e[b * TT + t0 + tid] = -1e30f;
        return;
    }
    for (int a = tid; a < AA; a += 256) {
        float v = 0.f;
#pragma unroll
        for (int p = 0; p < NSPK; p++) v += g_spart[p * BB * 3072 + b * 3072 + a];
        sE_s[a] = v;
        wee_s[a] = w_ee[a];
    }
    for (int i = tid; i < FCN * KCV; i += 256) convw_s[i] = conv_w[i];
    if (tid < FCN) convb_s[tid] = conv_b[tid];
    for (int i = tid; i < AA * FCN; i += 256) {
        int a = i >> 4, f = i & 15;
        WfeT[f * 516 + a] = W_fe[i];
    }
    if (tid < 132) {
        int tg = t0 - 50 + tid;
        alpha_s[tid] = (tg >= 0 && tg < TT) ? g_alpha[b * TT + tg] : 0.f;
    }
    __syncthreads();
    int w = tid >> 5, lane = tid & 31;
    for (int tt = w; tt < 32; tt += 8) {
        int tabs = t0 + tt;
        if (tabs >= len) {
            if (lane == 0) g_e[b * TT + tabs] = -1e30f;
            continue;
        }
        int f = lane & 15, half = lane >> 4;
        float yp = 0.f;
        int ks = half * 51, ke = half ? KCV : 51;
        for (int k = ks; k < ke; k++)
            yp = fmaf(alpha_s[tt + k], convw_s[f * KCV + k], yp);
        yp += __shfl_down_sync(0xffffffffu, yp, 16);
        if (half == 0) yp += convb_s[f];
        ull yp2[16];
#pragma unroll
        for (int ff = 0; ff < 16; ff++) yp2[ff] = pack2(__shfl_sync(0xffffffffu, yp, ff));
        const float* hEr = g_hE + ((size_t)b * TT + tabs) * AA;
        ull v2[8];
#pragma unroll
        for (int c = 0; c < 4; c++) {
            ulonglong2 h2 = *(const ulonglong2*)&hEr[c * 128 + lane * 4];
            ulonglong2 s2 = *(const ulonglong2*)&sE_s[c * 128 + lane * 4];
            v2[2 * c] = add2(h2.x, s2.x);
            v2[2 * c + 1] = add2(h2.y, s2.y);
        }
#pragma unroll
        for (int ff = 0; ff < 16; ff++) {
#pragma unroll
            for (int c = 0; c < 4; c++) {
                ulonglong2 w2 = *(const ulonglong2*)&WfeT[ff * 516 + c * 128 + lane * 4];
                fma2(v2[2 * c], yp2[ff], w2.x);
                fma2(v2[2 * c + 1], yp2[ff], w2.y);
            }
        }
        float acc = 0.f;
#pragma unroll
        for (int c = 0; c < 4; c++) {
            float4 we = *(const float4*)&wee_s[c * 128 + lane * 4];
            float2 a0 = unpk(v2[2 * c]);
            float2 a1 = unpk(v2[2 * c + 1]);
            acc = fmaf(tanh_fast(a0.x), we.x, acc);
            acc = fmaf(tanh_fast(a0.y), we.y, acc);
            acc = fmaf(tanh_fast(a1.x), we.z, acc);
            acc = fmaf(tanh_fast(a1.y), we.w, acc);
        }
#pragma unroll
        for (int off = 16; off; off >>= 1) acc += __shfl_down_sync(0xffffffffu, acc, off);
        if (lane == 0) g_e[b * TT + tabs] = acc;
    }
}

// ---------------- fused softmax + g = alpha @ hbatch (t-split x16) ----------------
__global__ __launch_bounds__(256) void k_gaccum(const float* __restrict__ hbatch,
                                                const int* __restrict__ lengths) {
    int b = blockIdx.x, ts = blockIdx.y;
    int tid = threadIdx.x;
    __shared__ float es[TT];
    __shared__ float red[256];
    float mx = -3e38f;
    for (int t2 = tid; t2 < TT; t2 += 256) {
        float v = g_e[b * TT + t2];
        es[t2] = v;
        mx = fmaxf(mx, v);
    }
    red[tid] = mx;
    __syncthreads();
    for (int o = 128; o; o >>= 1) {
        if (tid < o) red[tid] = fmaxf(red[tid], red[tid + o]);
        __syncthreads();
    }
    float M = red[0];
    __syncthreads();
    float sm = 0.f;
    for (int t2 = tid; t2 < TT; t2 += 256) {
        float p = __expf(es[t2] - M);
        es[t2] = p;
        sm += p;
    }
    red[tid] = sm;
    __syncthreads();
    for (int o = 128; o; o >>= 1) {
        if (tid < o) red[tid] += red[tid + o];
        __syncthreads();
    }
    float inv = 1.f / red[0];
    __syncthreads();
    for (int t2 = tid; t2 < TT; t2 += 256) es[t2] *= inv;
    __syncthreads();
    if (ts == 0)
        for (int t2 = tid; t2 < TT; t2 += 256) g_alpha[b * TT + t2] = es[t2];

    int len = lengths[b];
    int t1 = (len * ts) / NSPT, t2e = (len * (ts + 1)) / NSPT;
    int d = tid * 4;
    float4 acc = make_float4(0.f, 0.f, 0.f, 0.f);
    const float* hb = hbatch + (size_t)b * TT * DD + d;
    int t = t1;
    for (; t + 4 <= t2e; t += 4) {
        float a0 = es[t], a1 = es[t + 1], a2 = es[t + 2], a3 = es[t + 3];
        float4 h0 = *(const float4*)&hb[(size_t)t * DD];
        float4 h1 = *(const float4*)&hb[(size_t)(t + 1) * DD];
        float4 h2 = *(const float4*)&hb[(size_t)(t + 2) * DD];
        float4 h3 = *(const float4*)&hb[(size_t)(t + 3) * DD];
        acc.x = fmaf(a0, h0.x, fmaf(a1, h1.x, fmaf(a2, h2.x, fmaf(a3, h3.x, acc.x))));
        acc.y = fmaf(a0, h0.y, fmaf(a1, h1.y, fmaf(a2, h2.y, fmaf(a3, h3.y, acc.y))));
        acc.z = fmaf(a0, h0.z, fmaf(a1, h1.z, fmaf(a2, h2.z, fmaf(a3, h3.z, acc.z))));
        acc.w = fmaf(a0, h0.w, fmaf(a1, h1.w, fmaf(a2, h2.w, fmaf(a3, h3.w, acc.w))));
    }
    for (; t < t2e; t++) {
        float a0 = es[t];
        float4 h0 = *(const float4*)&hb[(size_t)t * DD];
        acc.x = fmaf(a0, h0.x, acc.x);
        acc.y = fmaf(a0, h0.y, acc.y);
        acc.z = fmaf(a0, h0.z, acc.z);
        acc.w = fmaf(a0, h0.w, acc.w);
    }
    *(float4*)&g_gp2[ts * BB * DD + b * DD + d] = acc;
}

// ---------------- LSTM cell + ypre (sums partials itself) ----------------
__global__ __launch_bounds__(512) void k_cell(const float* __restrict__ b_gy, int l) {
    int b = blockIdx.x, h = threadIdx.x;
    float gy = 0.f, sy = 0.f;
#pragma unroll
    for (int p = 0; p < NSPK; p++) {
        gy += g_gpart[p * BB * 2560 + b * 2560 + h];
        sy += g_spart[p * BB * 3072 + b * 3072 + 512 + h];
    }
    float ypre = tanhf(gy + sy + b_gy[h]);
    g_ypre_all[((size_t)l * BB + b) * HH + h] = ypre;
    float r[4];
#pragma unroll
    for (int q = 0; q < 4; q++) {
        int j = q * 512 + h;
        float v = g_recpre[((size_t)b * LL + l) * 2048 + j];
#pragma unroll
        for (int p = 0; p < NSPK; p++) {
            v += g_spart[p * BB * 3072 + b * 3072 + 1024 + j];
            v += g_gpart[p * BB * 2560 + b * 2560 + 512 + j];
        }
        r[q] = v;
    }
    float c = sig_acc(r[1]) * g_c[b * HH + h] + sig_acc(r[0]) * tanhf(r[2]);
    float s = sig_acc(r[3]) * tanhf(c);
    g_c[b * HH + h] = c;
    g_s[b * HH + h] = s;
}

// ---------------- launch ----------------
extern "C" void kernel_launch(void* const* d_in, const int* in_sizes, int n_in,
                              void* d_out, int out_size) {
    const float* hbatch  = (const float*)d_in[0];
    const int*   lengths = (const int*)d_in[1];
    const float* targets = (const float*)d_in[2];
    const float* W_sy    = (const float*)d_in[3];
    const float* W_gy    = (const float*)d_in[4];
    const float* b_gy    = (const float*)d_in[5];
    const float* W_yy    = (const float*)d_in[6];
    const float* b_yy    = (const float*)d_in[7];
    const float* W_ys    = (const float*)d_in[8];
    const float* W_ss    = (const float*)d_in[9];
    const float* W_gs    = (const float*)d_in[10];
    const float* b_gs    = (const float*)d_in[11];
    const float* W_se    = (const float*)d_in[12];
    const float* W_he    = (const float*)d_in[13];
    const float* W_fe    = (const float*)d_in[14];
    const float* conv_w  = (const float*)d_in[15];
    const float* conv_b  = (const float*)d_in[16];
    const float* w_ee    = (const float*)d_in[17];
    float* out = (float*)d_out;

    k_init<<<2048, 256>>>(W_se, W_sy, W_ss, W_gy, W_gs);
    // hE = hbatch @ W_he^T : [25600,512], K=1024
    k_gemm_big<0><<<dim3(4, 200), 256>>>(hbatch, W_he, nullptr, nullptr, 1024, 1024, 1024);
    // recpre = targets @ W_ys^T + b_gs : [1920,2048], K=4000
    k_gemm_big<1><<<dim3(16, 15), 256>>>(targets, W_ys, b_gs, nullptr, 4000, 4000, 4000);

    for (int l = 0; l < LL; l++) {
        k_skinny<0><<<dim3(12, NSPK), 256>>>();
        k_attn<<<dim3(25, 32), 256>>>(lengths, W_fe, conv_w, conv_b, w_ee);
        k_gaccum<<<dim3(32, NSPT), 256>>>(hbatch, lengths);
        k_gsum<<<32, 256>>>();
        k_skinny<1><<<dim3(10, NSPK), 256>>>();
        k_cell<<<32, 512>>>(b_gy, l);
    }
    // y = ypre_all @ W_yy^T + b_yy : [1920,4000], K=512 -> out
    k_gemm_big<2><<<dim3(32, 15), 256>>>(nullptr, W_yy, b_yy, out, 512, 512, 512);
}

// round 8
// speedup vs baseline: 1.7224x; 1.0288x over previous
#include <cuda_runtime.h>
#include <cstdint>

#define BB 32
#define TT 800
#define LL 60
#define HH 512
#define DD 1024
#define AA 512
#define FCN 16
#define KCV 101
#define CC 4000
#define NSPK 8
#define NSPT 16

typedef unsigned long long ull;

// ---------------- static device scratch ----------------
__device__ float g_hE[BB * TT * AA];
__device__ float g_recpre[BB * LL * 2048];
__device__ float g_WscatT[3072 * 512];   // [k/4][n][4] packed transposed
__device__ float g_WgcatT[2560 * 1024];  // [k/4][n][4] packed transposed
__device__ float g_spart[NSPK * BB * 3072];
__device__ float g_gpart[NSPK * BB * 2560];
__device__ float g_gp2[NSPT * BB * DD];
__device__ float g_g[BB * DD];
__device__ float g_e[BB * TT];
__device__ float g_alpha[BB * TT];
__device__ float g_ypre_all[LL * BB * HH];
__device__ float g_s[BB * HH];
__device__ float g_c[BB * HH];

__device__ __forceinline__ void fma2(ull& d, ull a, ull b) {
    asm("fma.rn.f32x2 %0, %1, %2, %0;" : "+l"(d) : "l"(a), "l"(b));
}
__device__ __forceinline__ ull add2(ull a, ull b) {
    ull r;
    asm("add.rn.f32x2 %0, %1, %2;" : "=l"(r) : "l"(a), "l"(b));
    return r;
}
__device__ __forceinline__ ull pack2(float x) {
    ull r;
    asm("mov.b64 %0, {%1, %1};" : "=l"(r) : "f"(x));
    return r;
}
__device__ __forceinline__ float2 unpk(ull v) {
    float2 f;
    asm("mov.b64 {%0,%1}, %2;" : "=f"(f.x), "=f"(f.y) : "l"(v));
    return f;
}
__device__ __forceinline__ float tanh_fast(float x) {
    float e2 = __expf(2.f * x);
    return 1.f - 2.f / (e2 + 1.f);
}
__device__ __forceinline__ float sig_acc(float x) {
    return tanhf(0.5f * x) * 0.5f + 0.5f;
}

// ---------------- init: zero state, build TRANSPOSED packed weights ----------------
__global__ void k_init(const float* __restrict__ W_se, const float* __restrict__ W_sy,
                       const float* __restrict__ W_ss, const float* __restrict__ W_gy,
                       const float* __restrict__ W_gs) {
    int i0 = blockIdx.x * blockDim.x + threadIdx.x;
    int st = gridDim.x * blockDim.x;
    for (int i = i0; i < BB * HH; i += st) { g_s[i] = 0.f; g_c[i] = 0.f; }
    for (int i = i0; i < BB * TT; i += st) g_alpha[i] = 0.f;
    // Wscat rows: [W_se(512); W_sy(512); W_ss(2048)], K=512
    for (int i = i0; i < 3072 * 512; i += st) {
        int r = i >> 9, k = i & 511;
        float v;
        if (r < 512)       v = W_se[i];
        else if (r < 1024) v = W_sy[(r - 512) * 512 + k];
        else               v = W_ss[(r - 1024) * 512 + k];
        g_WscatT[(((k >> 2) * 3072) + r) * 4 + (k & 3)] = v;
    }
    // Wgcat rows: [W_gy(512); W_gs(2048)], K=1024
    for (int i = i0; i < 2560 * 1024; i += st) {
        int r = i >> 10, k = i & 1023;
        float v = (r < 512) ? W_gy[i] : W_gs[(r - 512) * 1024 + k];
        g_WgcatT[(((k >> 2) * 2560) + r) * 4 + (k & 3)] = v;
    }
}

// ---------------- big GEMM (FFMA2): Out[M,N]=A[M,K]@W[N,K]^T ----------------
template <int MODE>
__global__ __launch_bounds__(256) void k_gemm_big(
    const float* __restrict__ A, const float* __restrict__ W,
    const float* __restrict__ bias, float* __restrict__ outx,
    int lda, int ldw, int K) {
    __shared__ __align__(16) float As[16][132];
    __shared__ __align__(16) float Bs[16][132];
    const float* Ap = (MODE == 2) ? g_ypre_all : A;
    int t = threadIdx.x;
    int n0 = blockIdx.x * 128, m0 = blockIdx.y * 128;
    int tr = t >> 4, tc = t & 15;
    ull acc2[4][8];
#pragma unroll
    for (int i = 0; i < 4; i++)
#pragma unroll
        for (int j = 0; j < 8; j++) acc2[i][j] = 0ull;

    for (int k0 = 0; k0 < K; k0 += 16) {
#pragma unroll
        for (int j = 0; j < 8; j++) {
            int e = t + j * 256;
            int m = e >> 4, k = e & 15;
            As[k][m] = Ap[(size_t)(m0 + m) * lda + k0 + k];
            int n = n0 + m;
            float wv = 0.f;
            if (MODE != 2 || n < CC) wv = W[(size_t)n * ldw + k0 + k];
            Bs[k][m] = wv;
        }
        __syncthreads();
#pragma unroll
        for (int k = 0; k < 16; k++) {
            ulonglong2 aA = *(const ulonglong2*)&As[k][tr * 8];
            ulonglong2 aB = *(const ulonglong2*)&As[k][tr * 8 + 4];
            ull ap[4] = {aA.x, aA.y, aB.x, aB.y};
            float4 b0 = *(const float4*)&Bs[k][tc * 8];
            float4 b1 = *(const float4*)&Bs[k][tc * 8 + 4];
            ull bp[8] = {pack2(b0.x), pack2(b0.y), pack2(b0.z), pack2(b0.w),
                         pack2(b1.x), pack2(b1.y), pack2(b1.z), pack2(b1.w)};
#pragma unroll
            for (int i = 0; i < 4; i++)
#pragma unroll
                for (int j = 0; j < 8; j++) fma2(acc2[i][j], ap[i], bp[j]);
        }
        __syncthreads();
    }
#pragma unroll
    for (int mp = 0; mp < 4; mp++) {
        float r0[8], r1[8];
#pragma unroll
        for (int j = 0; j < 8; j++) {
            float2 v = unpk(acc2[mp][j]);
            int n = n0 + tc * 8 + j;
            float bv = (MODE == 0) ? 0.f : ((MODE == 2 && n >= CC) ? 0.f : bias[n]);
            r0[j] = v.x + bv;
            r1[j] = v.y + bv;
        }
        int me = m0 + tr * 8 + 2 * mp;
        int nn = n0 + tc * 8;
#pragma unroll
        for (int rr = 0; rr < 2; rr++) {
            int m = me + rr;
            const float* src = rr ? r1 : r0;
            float* orow;
            if (MODE == 0)      orow = &g_hE[(size_t)m * 512];
            else if (MODE == 1) orow = &g_recpre[(size_t)m * 2048];
            else {
                int l = m >> 5, b = m & 31;
                orow = outx + (size_t)b * LL * CC + (size_t)l * CC;
            }
            if (MODE != 2 || nn + 7 < CC) {
                *(float4*)&orow[nn] = make_float4(src[0], src[1], src[2], src[3]);
                *(float4*)&orow[nn + 4] = make_float4(src[4], src[5], src[6], src[7]);
            } else {
#pragma unroll
                for (int j = 0; j < 8; j++)
                    if (nn + j < CC) orow[nn + j] = src[j];
            }
        }
    }
}

// ---------------- skinny GEMM: thread-per-n, k-major packed weights (coalesced) ----------------
// MODE 0: s @ Wscat^T (N=3072,K=512,KS=64)   grid (12,8)
// MODE 1: g @ Wgcat^T (N=2560,K=1024,KS=128) grid (10,8)
template <int MODE>
__global__ __launch_bounds__(256) void k_skinny() {
    constexpr int N = MODE ? 2560 : 3072;
    constexpr int K = MODE ? 1024 : 512;
    constexpr int KS = K / NSPK;
    constexpr int NBATCH = KS / 64;
    __shared__ __align__(16) float As[KS][36];
    int tid = threadIdx.x;
    int n = blockIdx.x * 256 + tid;
    int z = blockIdx.y, kb = z * KS;
    const float4* WT = (const float4*)(MODE ? g_WgcatT : g_WscatT);
    const float* Ain = MODE ? g_g : g_s;
    float* Out = MODE ? (g_gpart + z * BB * 2560) : (g_spart + z * BB * 3072);
    int kk0 = kb >> 2;

    // batch 0: 16 coalesced LDG.128, each warp covers 4 lines (not 32)
    float4 w[16];
#pragma unroll
    for (int i = 0; i < 16; i++) w[i] = WT[(size_t)(kk0 + i) * N + n];

    for (int i = tid; i < 32 * KS; i += 256) {
        int m = i / KS, k = i % KS;
        As[k][m] = Ain[m * K + kb + k];
    }
    __syncthreads();

    ull acc[16];
#pragma unroll
    for (int mp = 0; mp < 16; mp++) acc[mp] = 0ull;

#pragma unroll
    for (int bt = 0; bt < NBATCH; bt++) {
        if (bt > 0) {
#pragma unroll
            for (int i = 0; i < 16; i++)
                w[i] = WT[(size_t)(kk0 + bt * 16 + i) * N + n];
        }
#pragma unroll
        for (int k4 = 0; k4 < 16; k4++) {
            float wf[4] = {w[k4].x, w[k4].y, w[k4].z, w[k4].w};
#pragma unroll
            for (int q = 0; q < 4; q++) {
                ull wp = pack2(wf[q]);
                int k = bt * 64 + k4 * 4 + q;
#pragma unroll
                for (int mp = 0; mp < 16; mp++) {
                    ull a = *(const ull*)&As[k][2 * mp];
                    fma2(acc[mp], a, wp);
                }
            }
        }
    }
#pragma unroll
    for (int mp = 0; mp < 16; mp++) {
        float2 v = unpk(acc[mp]);
        Out[(2 * mp) * N + n] = v.x;
        Out[(2 * mp + 1) * N + n] = v.y;
    }
}

// ---------------- reduce t-split partials of g -> g_g ----------------
__global__ void k_gsum() {
    int b = blockIdx.x, d = threadIdx.x * 4;
    float4 acc = make_float4(0.f, 0.f, 0.f, 0.f);
#pragma unroll
    for (int p = 0; p < NSPT; p++) {
        float4 x = *(const float4*)&g_gp2[p * BB * DD + b * DD + d];
        acc.x += x.x; acc.y += x.y; acc.z += x.z; acc.w += x.w;
    }
    *(float4*)&g_g[b * DD + d] = acc;
}

// ---------------- fused attention scoring (sums sE partials itself) ----------------
__global__ __launch_bounds__(256) void k_attn(const int* __restrict__ lengths,
                                              const float* __restrict__ W_fe,
                                              const float* __restrict__ conv_w,
                                              const float* __restrict__ conv_b,
                                              const float* __restrict__ w_ee) {
    __shared__ float sE_s[AA];
    __shared__ float wee_s[AA];
    __shared__ float convw_s[FCN * KCV];
    __shared__ float convb_s[FCN];
    __shared__ float alpha_s[132];
    __shared__ __align__(16) float WfeT[FCN * 516];
    int b = blockIdx.y;
    int t0 = blockIdx.x * 32;
    int tid = threadIdx.x;
    int len = lengths[b];
    if (t0 >= len) {
        if (tid < 32) g_e[b * TT + t0 + tid] = -1e30f;
        return;
    }
    for (int a = tid; a < AA; a += 256) {
        float v = 0.f;
#pragma unroll
        for (int p = 0; p < NSPK; p++) v += g_spart[p * BB * 3072 + b * 3072 + a];
        sE_s[a] = v;
        wee_s[a] = w_ee[a];
    }
    for (int i = tid; i < FCN * KCV; i += 256) convw_s[i] = conv_w[i];
    if (tid < FCN) convb_s[tid] = conv_b[tid];
    for (int i = tid; i < AA * FCN; i += 256) {
        int a = i >> 4, f = i & 15;
        WfeT[f * 516 + a] = W_fe[i];
    }
    if (tid < 132) {
        int tg = t0 - 50 + tid;
        alpha_s[tid] = (tg >= 0 && tg < TT) ? g_alpha[b * TT + tg] : 0.f;
    }
    __syncthreads();
    int w = tid >> 5, lane = tid & 31;
    for (int tt = w; tt < 32; tt += 8) {
        int tabs = t0 + tt;
        if (tabs >= len) {
            if (lane == 0) g_e[b * TT + tabs] = -1e30f;
            continue;
        }
        int f = lane & 15, half = lane >> 4;
        float yp = 0.f;
        int ks = half * 51, ke = half ? KCV : 51;
        for (int k = ks; k < ke; k++)
            yp = fmaf(alpha_s[tt + k], convw_s[f * KCV + k], yp);
        yp += __shfl_down_sync(0xffffffffu, yp, 16);
        if (half == 0) yp += convb_s[f];
        ull yp2[16];
#pragma unroll
        for (int ff = 0; ff < 16; ff++) yp2[ff] = pack2(__shfl_sync(0xffffffffu, yp, ff));
        const float* hEr = g_hE + ((size_t)b * TT + tabs) * AA;
        ull v2[8];
#pragma unroll
        for (int c = 0; c < 4; c++) {
            ulonglong2 h2 = *(const ulonglong2*)&hEr[c * 128 + lane * 4];
            ulonglong2 s2 = *(const ulonglong2*)&sE_s[c * 128 + lane * 4];
            v2[2 * c] = add2(h2.x, s2.x);
            v2[2 * c + 1] = add2(h2.y, s2.y);
        }
#pragma unroll
        for (int ff = 0; ff < 16; ff++) {
#pragma unroll
            for (int c = 0; c < 4; c++) {
                ulonglong2 w2 = *(const ulonglong2*)&WfeT[ff * 516 + c * 128 + lane * 4];
                fma2(v2[2 * c], yp2[ff], w2.x);
                fma2(v2[2 * c + 1], yp2[ff], w2.y);
            }
        }
        float acc = 0.f;
#pragma unroll
        for (int c = 0; c < 4; c++) {
            float4 we = *(const float4*)&wee_s[c * 128 + lane * 4];
            float2 a0 = unpk(v2[2 * c]);
            float2 a1 = unpk(v2[2 * c + 1]);
            acc = fmaf(tanh_fast(a0.x), we.x, acc);
            acc = fmaf(tanh_fast(a0.y), we.y, acc);
            acc = fmaf(tanh_fast(a1.x), we.z, acc);
            acc = fmaf(tanh_fast(a1.y), we.w, acc);
        }
#pragma unroll
        for (int off = 16; off; off >>= 1) acc += __shfl_down_sync(0xffffffffu, acc, off);
        if (lane == 0) g_e[b * TT + tabs] = acc;
    }
}

// ---------------- fused softmax + g = alpha @ hbatch (t-split x16) ----------------
__global__ __launch_bounds__(256) void k_gaccum(const float* __restrict__ hbatch,
                                                const int* __restrict__ lengths) {
    int b = blockIdx.x, ts = blockIdx.y;
    int tid = threadIdx.x;
    __shared__ float es[TT];
    __shared__ float red[256];
    float mx = -3e38f;
    for (int t2 = tid; t2 < TT; t2 += 256) {
        float v = g_e[b * TT + t2];
        es[t2] = v;
        mx = fmaxf(mx, v);
    }
    red[tid] = mx;
    __syncthreads();
    for (int o = 128; o; o >>= 1) {
        if (tid < o) red[tid] = fmaxf(red[tid], red[tid + o]);
        __syncthreads();
    }
    float M = red[0];
    __syncthreads();
    float sm = 0.f;
    for (int t2 = tid; t2 < TT; t2 += 256) {
        float p = __expf(es[t2] - M);
        es[t2] = p;
        sm += p;
    }
    red[tid] = sm;
    __syncthreads();
    for (int o = 128; o; o >>= 1) {
        if (tid < o) red[tid] += red[tid + o];
        __syncthreads();
    }
    float inv = 1.f / red[0];
    __syncthreads();
    for (int t2 = tid; t2 < TT; t2 += 256) es[t2] *= inv;
    __syncthreads();
    if (ts == 0)
        for (int t2 = tid; t2 < TT; t2 += 256) g_alpha[b * TT + t2] = es[t2];

    int len = lengths[b];
    int t1 = (len * ts) / NSPT, t2e = (len * (ts + 1)) / NSPT;
    int d = tid * 4;
    float4 acc = make_float4(0.f, 0.f, 0.f, 0.f);
    const float* hb = hbatch + (size_t)b * TT * DD + d;
    int t = t1;
    for (; t + 4 <= t2e; t += 4) {
        float a0 = es[t], a1 = es[t + 1], a2 = es[t + 2], a3 = es[t + 3];
        float4 h0 = *(const float4*)&hb[(size_t)t * DD];
        float4 h1 = *(const float4*)&hb[(size_t)(t + 1) * DD];
        float4 h2 = *(const float4*)&hb[(size_t)(t + 2) * DD];
        float4 h3 = *(const float4*)&hb[(size_t)(t + 3) * DD];
        acc.x = fmaf(a0, h0.x, fmaf(a1, h1.x, fmaf(a2, h2.x, fmaf(a3, h3.x, acc.x))));
        acc.y = fmaf(a0, h0.y, fmaf(a1, h1.y, fmaf(a2, h2.y, fmaf(a3, h3.y, acc.y))));
        acc.z = fmaf(a0, h0.z, fmaf(a1, h1.z, fmaf(a2, h2.z, fmaf(a3, h3.z, acc.z))));
        acc.w = fmaf(a0, h0.w, fmaf(a1, h1.w, fmaf(a2, h2.w, fmaf(a3, h3.w, acc.w))));
    }
    for (; t < t2e; t++) {
        float a0 = es[t];
        float4 h0 = *(const float4*)&hb[(size_t)t * DD];
        acc.x = fmaf(a0, h0.x, acc.x);
        acc.y = fmaf(a0, h0.y, acc.y);
        acc.z = fmaf(a0, h0.z, acc.z);
        acc.w = fmaf(a0, h0.w, acc.w);
    }
    *(float4*)&g_gp2[ts * BB * DD + b * DD + d] = acc;
}

// ---------------- LSTM cell + ypre (sums partials itself) ----------------
__global__ __launch_bounds__(512) void k_cell(const float* __restrict__ b_gy, int l) {
    int b = blockIdx.x, h = threadIdx.x;
    float gy = 0.f, sy = 0.f;
#pragma unroll
    for (int p = 0; p < NSPK; p++) {
        gy += g_gpart[p * BB * 2560 + b * 2560 + h];
        sy += g_spart[p * BB * 3072 + b * 3072 + 512 + h];
    }
    float ypre = tanhf(gy + sy + b_gy[h]);
    g_ypre_all[((size_t)l * BB + b) * HH + h] = ypre;
    float r[4];
#pragma unroll
    for (int q = 0; q < 4; q++) {
        int j = q * 512 + h;
        float v = g_recpre[((size_t)b * LL + l) * 2048 + j];
#pragma unroll
        for (int p = 0; p < NSPK; p++) {
            v += g_spart[p * BB * 3072 + b * 3072 + 1024 + j];
            v += g_gpart[p * BB * 2560 + b * 2560 + 512 + j];
        }
        r[q] = v;
    }
    float c = sig_acc(r[1]) * g_c[b * HH + h] + sig_acc(r[0]) * tanhf(r[2]);
    float s = sig_acc(r[3]) * tanhf(c);
    g_c[b * HH + h] = c;
    g_s[b * HH + h] = s;
}

// ---------------- launch ----------------
extern "C" void kernel_launch(void* const* d_in, const int* in_sizes, int n_in,
                              void* d_out, int out_size) {
    const float* hbatch  = (const float*)d_in[0];
    const int*   lengths = (const int*)d_in[1];
    const float* targets = (const float*)d_in[2];
    const float* W_sy    = (const float*)d_in[3];
    const float* W_gy    = (const float*)d_in[4];
    const float* b_gy    = (const float*)d_in[5];
    const float* W_yy    = (const float*)d_in[6];
    const float* b_yy    = (const float*)d_in[7];
    const float* W_ys    = (const float*)d_in[8];
    const float* W_ss    = (const float*)d_in[9];
    const float* W_gs    = (const float*)d_in[10];
    const float* b_gs    = (const float*)d_in[11];
    const float* W_se    = (const float*)d_in[12];
    const float* W_he    = (const float*)d_in[13];
    const float* W_fe    = (const float*)d_in[14];
    const float* conv_w  = (const float*)d_in[15];
    const float* conv_b  = (const float*)d_in[16];
    const float* w_ee    = (const float*)d_in[17];
    float* out = (float*)d_out;

    k_init<<<2048, 256>>>(W_se, W_sy, W_ss, W_gy, W_gs);
    // hE = hbatch @ W_he^T : [25600,512], K=1024
    k_gemm_big<0><<<dim3(4, 200), 256>>>(hbatch, W_he, nullptr, nullptr, 1024, 1024, 1024);
    // recpre = targets @ W_ys^T + b_gs : [1920,2048], K=4000
    k_gemm_big<1><<<dim3(16, 15), 256>>>(targets, W_ys, b_gs, nullptr, 4000, 4000, 4000);

    for (int l = 0; l < LL; l++) {
        k_skinny<0><<<dim3(12, NSPK), 256>>>();
        k_attn<<<dim3(25, 32), 256>>>(lengths, W_fe, conv_w, conv_b, w_ee);
        k_gaccum<<<dim3(32, NSPT), 256>>>(hbatch, lengths);
        k_gsum<<<32, 256>>>();
        k_skinny<1><<<dim3(10, NSPK), 256>>>();
        k_cell<<<32, 512>>>(b_gy, l);
    }
    // y = ypre_all @ W_yy^T + b_yy : [1920,4000], K=512 -> out
    k_gemm_big<2><<<dim3(32, 15), 256>>>(nullptr, W_yy, b_yy, out, 512, 512, 512);
}